// round 12
// baseline (speedup 1.0000x reference)
#include <cuda_runtime.h>
#include <cuda_bf16.h>
#include <cstdint>

// ---------------- problem constants ----------------
#define NBINS       64
#define KDIM        192
#define FC          64
#define TILE_P      64
#define NTHREADS    512
#define MCAP        100000
#define Z_MIN_F     (-3.0f)
#define INV_BIN     16.0f
#define EPS_MEAN    1e-5f
#define EPS_BN      1e-5f

// ---- shared layout (float offsets) ----
// A0 [64][192], A1 [64][192]  : 2 x 12288
// Wt [64][192]                : 12288
// stage 2 x [64 pts][64 p] f2 : 2 x 8192
#define SM_A0    0
#define SM_A1    12288
#define SM_W     24576
#define SM_STG   36864
#define STG_F    8192                      // floats per stage buffer
#define SMEM_FLOATS (SM_STG + 2 * STG_F)   // 53248
#define SMEM_BYTES  (SMEM_FLOATS * 4)      // 212992 -> 1 CTA/SM

// named barriers: 1,2 = FULL[b]; 3,4 = EMPTY[b]; 5 = producer-internal
#define BAR_SYNC(id, cnt)   asm volatile("bar.sync %0, %1;"   :: "r"(id), "r"(cnt) : "memory")
#define BAR_ARRIVE(id, cnt) asm volatile("bar.arrive %0, %1;" :: "r"(id), "r"(cnt) : "memory")

// ---------------- global scratch ----------------
__device__ float4 g_X[MCAP * (FC / 4)];
__device__ float  g_sum[FC];
__device__ float  g_sqs[FC];
__device__ float  g_scale[FC];
__device__ float  g_shift[FC];

__device__ __forceinline__ float round_tf32(float x) {
    uint32_t u;
    asm("cvt.rna.tf32.f32 %0, %1;" : "=r"(u) : "f"(x));
    return __uint_as_float(u);
}
__device__ __forceinline__ uint32_t smem_u32(const void* p) {
    uint32_t a;
    asm("{ .reg .u64 t; cvta.to.shared.u64 t, %1; cvt.u32.u64 %0, t; }" : "=r"(a) : "l"(p));
    return a;
}
__device__ __forceinline__ void cp8(uint32_t saddr, const void* g) {
    asm volatile("cp.async.ca.shared.global [%0], [%1], 8;" :: "r"(saddr), "l"(g) : "memory");
}
__device__ __forceinline__ void cp_commit() {
    asm volatile("cp.async.commit_group;" ::: "memory");
}
__device__ __forceinline__ void cp_wait0() {
    asm volatile("cp.async.wait_group 0;" ::: "memory");
}

__device__ __forceinline__ void mma8(float* d, uint32_t a0, uint32_t a1,
                                     uint32_t a2, uint32_t a3,
                                     uint32_t b0, uint32_t b1) {
    asm volatile(
        "mma.sync.aligned.m16n8k8.row.col.f32.tf32.tf32.f32 "
        "{%0,%1,%2,%3}, {%4,%5,%6,%7}, {%8,%9}, {%0,%1,%2,%3};"
        : "+f"(d[0]), "+f"(d[1]), "+f"(d[2]), "+f"(d[3])
        : "r"(a0), "r"(a1), "r"(a2), "r"(a3), "r"(b0), "r"(b1));
}

// ---------------- kernel 1: warp-specialized hist/GEMM pipeline ----------------
__global__ void __launch_bounds__(NTHREADS)
main_kernel(const float* __restrict__ feat,
            const int*   __restrict__ nump,
            const float* __restrict__ W,
            const float* __restrict__ bbias,
            int M, int ntiles)
{
    extern __shared__ float sm[];
    float* Wt = sm + SM_W;
    float2* stage2 = (float2*)(sm + SM_STG);     // [2][64 pts][64 pillars]
    const uint32_t stg_b = smem_u32(sm) + SM_STG * 4;

    const int tid = threadIdx.x;
    const bool producer = (tid < 256);

    // ---- one-time: stage W (tf32-rounded, swizzled cols) ----
    {
        const float4* W4 = (const float4*)W;
        #pragma unroll
        for (int i = tid; i < (FC * KDIM) / 4; i += NTHREADS) {
            float4 v = W4[i];
            int c  = i / 48;
            int k4 = (i - c * 48) * 4;
            v.x = round_tf32(v.x); v.y = round_tf32(v.y);
            v.z = round_tf32(v.z); v.w = round_tf32(v.w);
            int colp = k4 ^ ((c & 7) << 2);
            *(float4*)(Wt + c * 192 + colp) = v;
        }
    }

    // consumer GEMM geometry (8 warps = 4 pillar-groups x 2 n-halves)
    const int ct    = tid - 256;                 // consumer-local id
    const int lane  = tid & 31;
    const int cwid  = (ct >= 0) ? (ct >> 5) : 0;
    const int nhalf = cwid >> 2;
    const int wpg   = cwid & 3;
    const int gid   = lane >> 2;
    const int tig   = lane & 3;
    const int gswz  = gid << 2;
    const int p0    = wpg * 16;
    const int cb    = nhalf * 32;

    float2 bias2[4];
    float2 s2[4], q2[4];
    #pragma unroll
    for (int j = 0; j < 4; j++) {
        s2[j] = make_float2(0.f, 0.f);
        q2[j] = make_float2(0.f, 0.f);
        bias2[j] = make_float2(0.f, 0.f);
    }
    if (!producer) {
        #pragma unroll
        for (int j = 0; j < 4; j++)
            bias2[j] = *(const float2*)(bbias + cb + j * 8 + 2 * tig);
    }

    // producer staging geometry: thread t<256 -> pillar t&63, point quarter t>>6
    const int sp = tid & 63;
    const int jq = tid >> 6;        // 0..3 for producers

    // hist geometry (producer threads 0..63; pillar = tid)
    const int hswz = (tid & 7) << 2;

    __syncthreads();                // Wt staged

    // pre-arm EMPTY barriers (consumers arrive once for each buffer)
    if (!producer) {
        BAR_ARRIVE(3, 512);
        BAR_ARRIVE(4, 512);
    } else {
        // prime: stage tile0 into stage[0]
        const int tile0 = blockIdx.x;
        if (tile0 < ntiles) {
            int gp = tile0 * TILE_P + sp;
            int np = (gp < M) ? nump[gp] : 0;
            const float* fb = feat + (size_t)gp * 256 + 2;
            #pragma unroll
            for (int u = 0; u < 16; u++) {
                int j = jq * 16 + u;
                if (j < np)
                    cp8(stg_b + (j * 64 + sp) * 8, fb + j * 4);
            }
        }
        cp_commit();
    }

    int k = 0;
    for (int tile = blockIdx.x; tile < ntiles; tile += gridDim.x, k++) {
        const int b    = k & 1;
        const int base = tile * TILE_P;
        float* Ab = sm + (b ? SM_A1 : SM_A0);

        if (producer) {
            // early loads (fly over the EMPTY wait)
            int np_h = 0;
            if (tid < TILE_P) {
                int gp = base + tid;
                np_h = (gp < M) ? nump[gp] : 0;
            }
            int nxt = tile + gridDim.x;
            int np_n = 0;
            if (nxt < ntiles) {
                int gp = nxt * TILE_P + sp;
                np_n = (gp < M) ? nump[gp] : 0;
            }

            BAR_SYNC(3 + b, 512);            // EMPTY[b]: consumer done with Ab
            // zero Ab
            {
                float4 z4 = make_float4(0.f, 0.f, 0.f, 0.f);
                float4* A4 = (float4*)Ab;
                #pragma unroll
                for (int i = tid; i < (TILE_P * KDIM) / 4; i += 256) A4[i] = z4;
            }
            cp_wait0();                      // own cp.asyncs done
            BAR_SYNC(5, 256);                // all producers' stage data visible + Ab zeroed

            // histogram: threads 0..63, pillar tid
            if (tid < TILE_P) {
                const float2* sbuf = stage2 + b * (STG_F / 2);
                float* hrow = Ab + tid * 192;
                for (int j = 0; j < np_h; j++) {
                    float2 v = sbuf[j * 64 + tid];
                    float z = v.x, r = v.y;
                    int bin = (int)((z - Z_MIN_F) * INV_BIN);
                    bin = max(0, min(NBINS - 1, bin));
                    int k3 = 3 * bin;
                    float* pc = hrow + ((k3)     ^ hswz);
                    float* pz = hrow + ((k3 + 1) ^ hswz);
                    float* pr = hrow + ((k3 + 2) ^ hswz);
                    float c0 = *pc;
                    float s0 = *pz;
                    float r0 = *pr;
                    *pc = c0 + 1.0f;
                    *pz = s0 + z;
                    *pr = r0 + r;
                }
            }
            BAR_SYNC(5, 256);                // hist complete; stage[b] consumed

            // issue next tile's stage into stage[b^1]
            if (nxt < ntiles) {
                const float* fb = feat + (size_t)(nxt * TILE_P + sp) * 256 + 2;
                uint32_t sb = stg_b + (b ^ 1) * (STG_F * 4 / 2) * 2 + 0; // see below
                // stage buffer byte base: stg_b + (b^1) * STG_F * 4
                sb = stg_b + (b ^ 1) * (STG_F * 4);
                #pragma unroll
                for (int u = 0; u < 16; u++) {
                    int j = jq * 16 + u;
                    if (j < np_n)
                        cp8(sb + (j * 64 + sp) * 8, fb + j * 4);
                }
            }
            cp_commit();

            // means (256 threads)
            #pragma unroll
            for (int idx = tid; idx < TILE_P * NBINS; idx += 256) {
                int bin = idx & 63;
                int p   = idx >> 6;
                int swz = (p & 7) << 2;
                float* row = Ab + p * 192;
                int k3 = 3 * bin;
                float* pc = row + ((k3)     ^ swz);
                float* pz = row + ((k3 + 1) ^ swz);
                float* pr = row + ((k3 + 2) ^ swz);
                float inv = __frcp_rn(*pc + EPS_MEAN);
                *pz = round_tf32(*pz * inv);
                *pr = round_tf32(*pr * inv);
            }
            BAR_ARRIVE(1 + b, 512);          // FULL[b]
        } else {
            BAR_SYNC(1 + b, 512);            // FULL[b]: Ab ready

            // GEMM: warp = m16 (p0..p0+15) x n32 (cb..cb+31)
            float d[4][4];
            #pragma unroll
            for (int j = 0; j < 4; j++) {
                d[j][0] = bias2[j].x; d[j][1] = bias2[j].y;
                d[j][2] = bias2[j].x; d[j][3] = bias2[j].y;
            }
            {
                const float* Ar0 = Ab + (p0 + gid) * 192;
                const float* Ar1 = Ar0 + 8 * 192;
                const float* Wg  = Wt + (cb + gid) * 192;
                #pragma unroll 4
                for (int s = 0; s < 24; s++) {
                    int col  = ((s << 3) | tig) ^ gswz;
                    int colx = col ^ 4;
                    uint32_t a0 = __float_as_uint(Ar0[col]);
                    uint32_t a1 = __float_as_uint(Ar1[col]);
                    uint32_t a2 = __float_as_uint(Ar0[colx]);
                    uint32_t a3 = __float_as_uint(Ar1[colx]);
                    #pragma unroll
                    for (int j = 0; j < 4; j++) {
                        const float* wr = Wg + j * (8 * 192);
                        uint32_t b0 = __float_as_uint(wr[col]);
                        uint32_t b1 = __float_as_uint(wr[colx]);
                        mma8(d[j], a0, a1, a2, a3, b0, b1);
                    }
                }
            }
            BAR_ARRIVE(3 + b, 512);          // EMPTY[b]: done reading Ab

            // epilogue off the critical path: store x + BN accumulation
            {
                int gp0 = base + p0 + gid;
                int gp1 = gp0 + 8;
                float2* gx = (float2*)g_X;
                int co = nhalf * 16;
                if (gp0 < M) {
                    #pragma unroll
                    for (int j = 0; j < 4; j++) {
                        gx[gp0 * 32 + co + j * 4 + tig] = make_float2(d[j][0], d[j][1]);
                        s2[j].x += d[j][0]; s2[j].y += d[j][1];
                        q2[j].x += d[j][0] * d[j][0];
                        q2[j].y += d[j][1] * d[j][1];
                    }
                }
                if (gp1 < M) {
                    #pragma unroll
                    for (int j = 0; j < 4; j++) {
                        gx[gp1 * 32 + co + j * 4 + tig] = make_float2(d[j][2], d[j][3]);
                        s2[j].x += d[j][2]; s2[j].y += d[j][3];
                        q2[j].x += d[j][2] * d[j][2];
                        q2[j].y += d[j][3] * d[j][3];
                    }
                }
            }
        }
    }

    // ---- final BN reduction (consumer partials) ----
    __syncthreads();
    float2* Ssm = (float2*)sm;       // A0 region dead
    float2* Qsm = Ssm + 1024;
    if (!producer) {
        #pragma unroll
        for (int j = 0; j < 4; j++) {
            Ssm[ct * 4 + j] = s2[j];
            Qsm[ct * 4 + j] = q2[j];
        }
    }
    __syncthreads();
    if (tid < FC) {
        int c  = tid;
        int nh = c >> 5;
        int jj = (c & 31) >> 3;
        int tg = (c >> 1) & 3;
        int e  = c & 1;
        float ts = 0.f, tq = 0.f;
        #pragma unroll
        for (int w = 0; w < 4; w++) {
            #pragma unroll
            for (int g = 0; g < 8; g++) {
                int src = (((nh * 4 + w) << 5) + (g << 2) + tg) * 4 + jj;
                float2 vs = Ssm[src];
                float2 vq = Qsm[src];
                ts += e ? vs.y : vs.x;
                tq += e ? vq.y : vq.x;
            }
        }
        atomicAdd(&g_sum[c], ts);
        atomicAdd(&g_sqs[c], tq);
    }
}

// ---------------- kernel 2: finalize BN scale/shift ----------------
__global__ void finalize_kernel(const float* __restrict__ gamma,
                                const float* __restrict__ beta,
                                int M)
{
    int c = threadIdx.x;
    if (c < FC) {
        float invM = 1.0f / (float)M;
        float mu   = g_sum[c] * invM;
        float var  = g_sqs[c] * invM - mu * mu;
        var = fmaxf(var, 0.0f);
        float sc = gamma[c] * rsqrtf(var + EPS_BN);
        g_scale[c] = sc;
        g_shift[c] = beta[c] - mu * sc;
    }
}

// ---------------- kernel 3: normalize + ReLU + reset accumulators ----------------
__global__ void __launch_bounds__(256)
apply_kernel(float4* __restrict__ out, int M)
{
    int n4 = M * (FC / 4);
    int gid = blockIdx.x * blockDim.x + threadIdx.x;
    int stride = gridDim.x * blockDim.x;

    float4 x[4];
    int idx[4];
    #pragma unroll
    for (int u = 0; u < 4; u++) {
        int i = gid + u * stride;
        idx[u] = i;
        if (i < n4) x[u] = g_X[i];
    }
    #pragma unroll
    for (int u = 0; u < 4; u++) {
        int i = idx[u];
        if (i < n4) {
            int cbq = (i & 15) * 4;
            float4 sc = *(const float4*)&g_scale[cbq];
            float4 sh = *(const float4*)&g_shift[cbq];
            float4 r;
            r.x = fmaxf(fmaf(x[u].x, sc.x, sh.x), 0.0f);
            r.y = fmaxf(fmaf(x[u].y, sc.y, sh.y), 0.0f);
            r.z = fmaxf(fmaf(x[u].z, sc.z, sh.z), 0.0f);
            r.w = fmaxf(fmaf(x[u].w, sc.w, sh.w), 0.0f);
            out[i] = r;
        }
    }
    if (blockIdx.x == 0 && threadIdx.x < FC) {
        g_sum[threadIdx.x] = 0.0f;
        g_sqs[threadIdx.x] = 0.0f;
    }
}

// ---------------- launch ----------------
extern "C" void kernel_launch(void* const* d_in, const int* in_sizes, int n_in,
                              void* d_out, int out_size)
{
    const float* feat  = (const float*)d_in[0];
    const int*   nump  = (const int*)  d_in[1];
    const float* W     = (const float*)d_in[3];
    const float* bbias = (const float*)d_in[4];
    const float* gamma = (const float*)d_in[5];
    const float* beta  = (const float*)d_in[6];
    float4* out = (float4*)d_out;

    int M = in_sizes[1];
    if (M > MCAP) M = MCAP;
    int ntiles = (M + TILE_P - 1) / TILE_P;

    cudaFuncSetAttribute(main_kernel, cudaFuncAttributeMaxDynamicSharedMemorySize, SMEM_BYTES);

    int grid = ntiles < 148 ? ntiles : 148;
    main_kernel<<<grid, NTHREADS, SMEM_BYTES>>>(feat, nump, W, bbias, M, ntiles);
    finalize_kernel<<<1, 64>>>(gamma, beta, M);
    int n4 = M * (FC / 4);
    int blocks = ((n4 + 3) / 4 + 255) / 256;
    apply_kernel<<<blocks, 256>>>(out, M);
}

// round 13
// speedup vs baseline: 1.3237x; 1.3237x over previous
#include <cuda_runtime.h>
#include <cuda_bf16.h>
#include <cstdint>

// ---------------- problem constants ----------------
#define NBINS       64
#define KDIM        192
#define FC          64
#define TILE_P      128
#define NTHREADS    512
#define MCAP        100000
#define Z_MIN_F     (-3.0f)
#define INV_BIN     16.0f
#define EPS_MEAN    1e-5f
#define EPS_BN      1e-5f

// ---- shared layout (float offsets) ----
// At  [128][192] swizzled mma A operand   24576 (96KB)
// Wt  [ 64][192] swizzled mma B operand   12288 (48KB)
// stg ring of 3 x [128 pillars][17 f2]    3*4352 floats (52.2KB)
#define SM_AT    0
#define SM_W     24576
#define SM_STG   36864
#define STG_BUF  4352                        // floats per ring buffer (128*17*2)
#define STG_BUF_B (STG_BUF * 4)              // 17408 bytes
#define SMEM_FLOATS (SM_STG + 3 * STG_BUF)   // 49920
#define SMEM_BYTES  (SMEM_FLOATS * 4)        // 199680 -> 1 CTA/SM

// ---------------- global scratch ----------------
__device__ float4 g_X[MCAP * (FC / 4)];
__device__ float  g_sum[FC];
__device__ float  g_sqs[FC];
__device__ float  g_scale[FC];
__device__ float  g_shift[FC];

__device__ __forceinline__ float round_tf32(float x) {
    uint32_t u;
    asm("cvt.rna.tf32.f32 %0, %1;" : "=r"(u) : "f"(x));
    return __uint_as_float(u);
}
__device__ __forceinline__ uint32_t smem_u32(const void* p) {
    uint32_t a;
    asm("{ .reg .u64 t; cvta.to.shared.u64 t, %1; cvt.u32.u64 %0, t; }" : "=r"(a) : "l"(p));
    return a;
}
__device__ __forceinline__ void cp8(uint32_t saddr, const void* g) {
    asm volatile("cp.async.ca.shared.global [%0], [%1], 8;" :: "r"(saddr), "l"(g) : "memory");
}
__device__ __forceinline__ void cp_commit() {
    asm volatile("cp.async.commit_group;" ::: "memory");
}
__device__ __forceinline__ void cp_wait1() {
    asm volatile("cp.async.wait_group 1;" ::: "memory");
}

__device__ __forceinline__ void mma8(float* d, uint32_t a0, uint32_t a1,
                                     uint32_t a2, uint32_t a3,
                                     uint32_t b0, uint32_t b1) {
    asm volatile(
        "mma.sync.aligned.m16n8k8.row.col.f32.tf32.tf32.f32 "
        "{%0,%1,%2,%3}, {%4,%5,%6,%7}, {%8,%9}, {%0,%1,%2,%3};"
        : "+f"(d[0]), "+f"(d[1]), "+f"(d[2]), "+f"(d[3])
        : "r"(a0), "r"(a1), "r"(a2), "r"(a3), "r"(b0), "r"(b1));
}

// ---------------- kernel 1: persistent hist + tf32 mma GEMM + fused BN ----------------
__global__ void __launch_bounds__(NTHREADS)
main_kernel(const float* __restrict__ feat,
            const int*   __restrict__ nump,
            const float* __restrict__ W,
            const float* __restrict__ bbias,
            int M, int ntiles)
{
    extern __shared__ float sm[];
    float* At = sm + SM_AT;
    float* Wt = sm + SM_W;
    float2* stage2 = (float2*)(sm + SM_STG);
    const uint32_t stg_b = smem_u32(sm) + SM_STG * 4;

    const int tid = threadIdx.x;

    // ---- one-time: stage W (tf32-rounded, swizzled cols) ----
    {
        const float4* W4 = (const float4*)W;
        #pragma unroll
        for (int i = tid; i < (FC * KDIM) / 4; i += NTHREADS) {
            float4 v = W4[i];
            int c  = i / 48;
            int k4 = (i - c * 48) * 4;
            v.x = round_tf32(v.x); v.y = round_tf32(v.y);
            v.z = round_tf32(v.z); v.w = round_tf32(v.w);
            int colp = k4 ^ ((c & 7) << 2);
            *(float4*)(Wt + c * 192 + colp) = v;
        }
    }

    // GEMM thread geometry: 16 warps = 8 pillar-groups x 2 n-halves
    const int lane  = tid & 31;
    const int wid   = tid >> 5;
    const int nhalf = wid >> 3;
    const int wpg   = wid & 7;
    const int gid   = lane >> 2;
    const int tig   = lane & 3;
    const int gswz  = gid << 2;
    const int p0    = wpg * 16;
    const int cb    = nhalf * 32;

    float2 bias2[4];
    #pragma unroll
    for (int j = 0; j < 4; j++)
        bias2[j] = *(const float2*)(bbias + cb + j * 8 + 2 * tig);

    float2 s2[4], q2[4];
    #pragma unroll
    for (int j = 0; j < 4; j++) {
        s2[j] = make_float2(0.f, 0.f);
        q2[j] = make_float2(0.f, 0.f);
    }

    // staging geometry: element e = tid + u*512 (u=0..3) -> pillar e>>4, point e&15
    const int sp = tid >> 4;           // pillar base: sp + 32u
    const int j0 = tid & 15;           // point-in-chunk

    // hist geometry (threads 0..127; pillar = tid)
    const int hswz = (tid & 7) << 2;
    float* hrow = At + tid * 192;

    int np_cur[4] = {0, 0, 0, 0};
    int np_nxt[4] = {0, 0, 0, 0};
    int isl = 0;                       // ring slot of next issued chunk
    int csl = 0;                       // ring slot of next consumed chunk

    // ---- prime: first tile's chunks 0,1 (16 points each) ----
    const int tile0 = blockIdx.x;
    if (tile0 < ntiles) {
        const int b0 = tile0 * TILE_P;
        #pragma unroll
        for (int u = 0; u < 4; u++) {
            int gp = b0 + sp + u * 32;
            np_cur[u] = (gp < M) ? nump[gp] : 0;
        }
        #pragma unroll
        for (int c0 = 0; c0 < 2; c0++) {
            #pragma unroll
            for (int u = 0; u < 4; u++) {
                int p = sp + u * 32;
                int jj = c0 * 16 + j0;
                if (jj < np_cur[u])
                    cp8(stg_b + isl * STG_BUF_B + (p * 17 + j0) * 8,
                        feat + (size_t)(b0 + p) * 256 + jj * 4 + 2);
            }
            cp_commit();
            isl = (isl + 1 < 3) ? isl + 1 : 0;
        }
    }

    for (int tile = tile0; tile < ntiles; tile += gridDim.x) {
        const int base  = tile * TILE_P;
        const int nxt   = tile + gridDim.x;
        const int nbase = nxt * TILE_P;

        const int npt = (tid < TILE_P && base + tid < M) ? nump[base + tid] : 0;

        __syncthreads();               // prev GEMM done -> At reusable
        // zero At while staged cp.asyncs fly
        {
            float4 z4 = make_float4(0.f, 0.f, 0.f, 0.f);
            float4* A4 = (float4*)At;
            #pragma unroll
            for (int i = tid; i < (TILE_P * KDIM) / 4; i += NTHREADS) A4[i] = z4;
        }

        // ---- 4 chunk phases (16 points each), continuous ring-3 pipeline ----
        #pragma unroll
        for (int ch = 0; ch < 4; ch++) {
            if (ch == 0) {             // prefetch next tile's num_points early
                #pragma unroll
                for (int u = 0; u < 4; u++) {
                    int gp = nbase + sp + u * 32;
                    np_nxt[u] = (nxt < ntiles && gp < M) ? nump[gp] : 0;
                }
            }
            cp_wait1();                // chunk ch resident
            __syncthreads();
            // issue next chunk in sequence (ch+2 of this tile, or 0/1 of next tile)
            {
                const bool  this_t = (ch < 2);
                const int   cn     = this_t ? (ch + 2) : (ch - 2);
                const int   tb     = this_t ? base : nbase;
                const int*  np     = this_t ? np_cur : np_nxt;
                const bool  live   = this_t || (nxt < ntiles);
                if (live) {
                    #pragma unroll
                    for (int u = 0; u < 4; u++) {
                        int p = sp + u * 32;
                        int jj = cn * 16 + j0;
                        if (jj < np[u])
                            cp8(stg_b + isl * STG_BUF_B + (p * 17 + j0) * 8,
                                feat + (size_t)(tb + p) * 256 + jj * 4 + 2);
                    }
                }
                cp_commit();
                isl = (isl + 1 < 3) ? isl + 1 : 0;
            }
            // histogram chunk ch (threads 0..127, 16 points)
            if (tid < TILE_P) {
                const float2* buf = stage2 + csl * (STG_BUF / 2) + tid * 17;
                #pragma unroll 4
                for (int j = 0; j < 16; j++) {
                    if (ch * 16 + j < npt) {
                        float2 v = buf[j];
                        float z = v.x, r = v.y;
                        int bin = (int)((z - Z_MIN_F) * INV_BIN);
                        bin = max(0, min(NBINS - 1, bin));
                        int k3 = 3 * bin;
                        float* pc = hrow + ((k3)     ^ hswz);
                        float* pz = hrow + ((k3 + 1) ^ hswz);
                        float* pr = hrow + ((k3 + 2) ^ hswz);
                        float c0 = *pc;
                        float s0 = *pz;
                        float r0 = *pr;
                        *pc = c0 + 1.0f;
                        *pz = s0 + z;
                        *pr = r0 + r;
                    }
                }
            }
            csl = (csl + 1 < 3) ? csl + 1 : 0;
        }
        #pragma unroll
        for (int u = 0; u < 4; u++) np_cur[u] = np_nxt[u];
        __syncthreads();               // At complete

        // ---- sums -> means, tf32-rounded ----
        #pragma unroll
        for (int idx = tid; idx < TILE_P * NBINS; idx += NTHREADS) {
            int bin = idx & 63;
            int p   = idx >> 6;
            int swz = (p & 7) << 2;
            float* row = At + p * 192;
            int k3 = 3 * bin;
            float* pc = row + ((k3)     ^ swz);
            float* pz = row + ((k3 + 1) ^ swz);
            float* pr = row + ((k3 + 2) ^ swz);
            float inv = __frcp_rn(*pc + EPS_MEAN);
            *pz = round_tf32(*pz * inv);
            *pr = round_tf32(*pr * inv);
        }
        __syncthreads();

        // ---- GEMM: warp = m16 (p0..p0+15) x n32 (cb..cb+31) ----
        float d[4][4];
        #pragma unroll
        for (int j = 0; j < 4; j++) {
            d[j][0] = bias2[j].x; d[j][1] = bias2[j].y;
            d[j][2] = bias2[j].x; d[j][3] = bias2[j].y;
        }
        {
            const float* Ar0 = At + (p0 + gid) * 192;
            const float* Ar1 = Ar0 + 8 * 192;
            const float* Wg  = Wt + (cb + gid) * 192;
            #pragma unroll 4
            for (int s = 0; s < 24; s++) {
                int col  = ((s << 3) | tig) ^ gswz;
                int colx = col ^ 4;
                uint32_t a0 = __float_as_uint(Ar0[col]);
                uint32_t a1 = __float_as_uint(Ar1[col]);
                uint32_t a2 = __float_as_uint(Ar0[colx]);
                uint32_t a3 = __float_as_uint(Ar1[colx]);
                #pragma unroll
                for (int j = 0; j < 4; j++) {
                    const float* wr = Wg + j * (8 * 192);
                    uint32_t b0 = __float_as_uint(wr[col]);
                    uint32_t b1 = __float_as_uint(wr[colx]);
                    mma8(d[j], a0, a1, a2, a3, b0, b1);
                }
            }
        }

        // ---- epilogue: store x + BN register accumulation ----
        {
            int gp0 = base + p0 + gid;
            int gp1 = gp0 + 8;
            float2* gx = (float2*)g_X;
            int co = nhalf * 16;
            if (gp0 < M) {
                #pragma unroll
                for (int j = 0; j < 4; j++) {
                    gx[gp0 * 32 + co + j * 4 + tig] = make_float2(d[j][0], d[j][1]);
                    s2[j].x += d[j][0]; s2[j].y += d[j][1];
                    q2[j].x += d[j][0] * d[j][0];
                    q2[j].y += d[j][1] * d[j][1];
                }
            }
            if (gp1 < M) {
                #pragma unroll
                for (int j = 0; j < 4; j++) {
                    gx[gp1 * 32 + co + j * 4 + tig] = make_float2(d[j][2], d[j][3]);
                    s2[j].x += d[j][2]; s2[j].y += d[j][3];
                    q2[j].x += d[j][2] * d[j][2];
                    q2[j].y += d[j][3] * d[j][3];
                }
            }
        }
    }

    // ---- final BN reduction: regs -> smem -> global atomics ----
    __syncthreads();
    float2* Ssm = (float2*)sm;       // At region dead
    float2* Qsm = Ssm + 2048;
    #pragma unroll
    for (int j = 0; j < 4; j++) {
        Ssm[tid * 4 + j] = s2[j];
        Qsm[tid * 4 + j] = q2[j];
    }
    __syncthreads();
    if (tid < FC) {
        int c  = tid;
        int nh = c >> 5;
        int jj = (c & 31) >> 3;
        int tg = (c >> 1) & 3;
        int e  = c & 1;
        float ts = 0.f, tq = 0.f;
        #pragma unroll
        for (int w = 0; w < 8; w++) {
            #pragma unroll
            for (int g = 0; g < 8; g++) {
                int src = ((nh * 8 + w) * 32 + g * 4 + tg) * 4 + jj;
                float2 vs = Ssm[src];
                float2 vq = Qsm[src];
                ts += e ? vs.y : vs.x;
                tq += e ? vq.y : vq.x;
            }
        }
        atomicAdd(&g_sum[c], ts);
        atomicAdd(&g_sqs[c], tq);
    }
}

// ---------------- kernel 2: finalize BN scale/shift ----------------
__global__ void finalize_kernel(const float* __restrict__ gamma,
                                const float* __restrict__ beta,
                                int M)
{
    int c = threadIdx.x;
    if (c < FC) {
        float invM = 1.0f / (float)M;
        float mu   = g_sum[c] * invM;
        float var  = g_sqs[c] * invM - mu * mu;
        var = fmaxf(var, 0.0f);
        float sc = gamma[c] * rsqrtf(var + EPS_BN);
        g_scale[c] = sc;
        g_shift[c] = beta[c] - mu * sc;
    }
}

// ---------------- kernel 3: normalize + ReLU + reset accumulators ----------------
__global__ void __launch_bounds__(256)
apply_kernel(float4* __restrict__ out, int M)
{
    int n4 = M * (FC / 4);
    int gid = blockIdx.x * blockDim.x + threadIdx.x;
    int stride = gridDim.x * blockDim.x;

    float4 x[4];
    int idx[4];
    #pragma unroll
    for (int u = 0; u < 4; u++) {
        int i = gid + u * stride;
        idx[u] = i;
        if (i < n4) x[u] = g_X[i];
    }
    #pragma unroll
    for (int u = 0; u < 4; u++) {
        int i = idx[u];
        if (i < n4) {
            int cbq = (i & 15) * 4;
            float4 sc = *(const float4*)&g_scale[cbq];
            float4 sh = *(const float4*)&g_shift[cbq];
            float4 r;
            r.x = fmaxf(fmaf(x[u].x, sc.x, sh.x), 0.0f);
            r.y = fmaxf(fmaf(x[u].y, sc.y, sh.y), 0.0f);
            r.z = fmaxf(fmaf(x[u].z, sc.z, sh.z), 0.0f);
            r.w = fmaxf(fmaf(x[u].w, sc.w, sh.w), 0.0f);
            out[i] = r;
        }
    }
    if (blockIdx.x == 0 && threadIdx.x < FC) {
        g_sum[threadIdx.x] = 0.0f;
        g_sqs[threadIdx.x] = 0.0f;
    }
}

// ---------------- launch ----------------
extern "C" void kernel_launch(void* const* d_in, const int* in_sizes, int n_in,
                              void* d_out, int out_size)
{
    const float* feat  = (const float*)d_in[0];
    const int*   nump  = (const int*)  d_in[1];
    const float* W     = (const float*)d_in[3];
    const float* bbias = (const float*)d_in[4];
    const float* gamma = (const float*)d_in[5];
    const float* beta  = (const float*)d_in[6];
    float4* out = (float4*)d_out;

    int M = in_sizes[1];
    if (M > MCAP) M = MCAP;
    int ntiles = (M + TILE_P - 1) / TILE_P;

    cudaFuncSetAttribute(main_kernel, cudaFuncAttributeMaxDynamicSharedMemorySize, SMEM_BYTES);

    int grid = ntiles < 148 ? ntiles : 148;
    main_kernel<<<grid, NTHREADS, SMEM_BYTES>>>(feat, nump, W, bbias, M, ntiles);
    finalize_kernel<<<1, 64>>>(gamma, beta, M);
    int n4 = M * (FC / 4);
    int blocks = ((n4 + 3) / 4 + 255) / 256;
    apply_kernel<<<blocks, 256>>>(out, M);
}